// round 12
// baseline (speedup 1.0000x reference)
#include <cuda_runtime.h>
#include <cstdint>

#define B 32
#define HW 512
#define NPATCH 4
#define C 3
#define P 128
#define HALF 64
#define MARGIN 32
#define TILE 32
#define TPD (HW / TILE)          // 16
#define NTILE (TPD * TPD)        // 256
#define NHALF (NTILE * 2)        // 512 half-tiles per map (16x32 px)
#define PATCH_OUT_ELEMS (B * NPATCH * C * P * P)

#define BPB 16                   // blocks per batch
#define GRID (B * BPB)           // 512 <= 148*4 -> all co-resident

__device__ unsigned long long g_half[B * NHALF];
__device__ int g_boxes[B * NPATCH * 4];
__device__ int g_cnt[B];         // scan-complete counters (reset by consumer)
__device__ int g_flag[B];        // boxes-ready flags     (reset by consumer)
__device__ int g_done[B];        // extract-complete      (reset by consumer)

__device__ __forceinline__ unsigned flipf(float v) {
    unsigned ub = __float_as_uint(v);
    return (ub & 0x80000000u) ? ~ub : (ub | 0x80000000u);
}

// ---------------------------------------------------------------------------
// One persistent kernel: scan -> (per-batch) select -> extract, linked by
// per-batch flags. No global barrier; all blocks guaranteed resident.
// ---------------------------------------------------------------------------
__global__ __launch_bounds__(256, 4)
void k_fused(const float* __restrict__ images,
             const float* __restrict__ umap,
             float* __restrict__ out,
             float* __restrict__ out_coords) {
    const int b = blockIdx.x >> 4;          // batch
    const int i = blockIdx.x & (BPB - 1);   // block within batch
    const int t = threadIdx.x;
    const int lane = t & 31, wid = t >> 5;
    const float* __restrict__ um = umap + ((size_t)b << 18);

    // ---------------- Phase 1: scan 32 half-tiles of batch b ----------------
#pragma unroll
    for (int rep = 0; rep < 4; rep++) {
        const int hid = i * 32 + rep * 8 + wid;           // 0..511
        const int tile = hid >> 1;
        const int tx1 = (tile & (TPD - 1)) * TILE;
        const int ty1 = ((tile >> 4) * TILE) + ((hid & 1) << 4);

        float4 f[4];
#pragma unroll
        for (int q = 0; q < 4; q++) {
            const int f4 = q * 32 + lane;                 // 0..127
            const int y = ty1 + (f4 >> 3);
            const int x = tx1 + ((f4 & 7) << 2);
            f[q] = *(const float4*)(um + (y << 9) + x);
        }
        float c4[4];
#pragma unroll
        for (int q = 0; q < 4; q++)
            c4[q] = fmaxf(fmaxf(f[q].x, f[q].y), fmaxf(f[q].z, f[q].w));
        const float m = fmaxf(fmaxf(c4[0], c4[1]), fmaxf(c4[2], c4[3]));

        const unsigned fm = flipf(m);
        const unsigned rmax = __reduce_max_sync(0xFFFFFFFFu, fm);

        int idx = 0x7FFFFFFF;
        if (fm == rmax) {
#pragma unroll
            for (int q = 0; q < 4; q++) {
                if (c4[q] == m) {
                    const int f4 = q * 32 + lane;
                    const int gi = ((ty1 + (f4 >> 3)) << 9) + tx1 + ((f4 & 7) << 2);
                    if (f[q].x == m) idx = min(idx, gi);
                    if (f[q].y == m) idx = min(idx, gi + 1);
                    if (f[q].z == m) idx = min(idx, gi + 2);
                    if (f[q].w == m) idx = min(idx, gi + 3);
                }
            }
        }
        const unsigned rid = __reduce_min_sync(0xFFFFFFFFu, (unsigned)idx);
        if (lane == 0)
            g_half[b * NHALF + hid] =
                ((unsigned long long)rmax << 32) | (unsigned)~rid;
    }
    __syncthreads();
    if (t == 0) { __threadfence(); atomicAdd(&g_cnt[b], 1); }

    // ---------------- Phase 2: select (block i==0 of each batch) ------------
    __shared__ unsigned long long stile[NTILE];
    __shared__ unsigned long long sred[8];
    __shared__ int sebox[NPATCH][4];
    __shared__ int slist[64];
    __shared__ int scount;

    if (i == 0) {
        if (t == 0) {
            while (atomicAdd(&g_cnt[b], 0) < BPB) __nanosleep(32);
            g_cnt[b] = 0;                      // consumer resets for next call
        }
        __syncthreads();
        __threadfence();

        {
            const unsigned long long a = g_half[b * NHALF + 2 * t];
            const unsigned long long c = g_half[b * NHALF + 2 * t + 1];
            stile[t] = (a > c) ? a : c;        // order preserves first-occurrence
        }

        for (int k = 0; k < NPATCH; k++) {
            __syncthreads();
            unsigned long long v = stile[t];
#pragma unroll
            for (int off = 16; off > 0; off >>= 1) {
                unsigned long long o = __shfl_down_sync(0xFFFFFFFFu, v, off);
                v = (o > v) ? o : v;
            }
            if (lane == 0) sred[wid] = v;
            __syncthreads();
            if (t == 0) {
                unsigned long long w = sred[0];
#pragma unroll
                for (int j = 1; j < 8; j++) w = (sred[j] > w) ? sred[j] : w;
                const int idx = (int)(~(unsigned)(w & 0xFFFFFFFFu));
                const int yc = idx >> 9, xc = idx & (HW - 1);

                int x1 = max(0, xc - HALF), x2 = min(HW, xc + HALF);
                if (x2 - x1 < P) { if (x1 == 0) x2 = P; else x1 = x2 - P; }
                int y1 = max(0, yc - HALF), y2 = min(HW, yc + HALF);
                if (y2 - y1 < P) { if (y1 == 0) y2 = P; else y1 = y2 - P; }

                sebox[k][0] = x1 - MARGIN; sebox[k][1] = y1 - MARGIN;
                sebox[k][2] = x2 + MARGIN; sebox[k][3] = y2 + MARGIN;

                int* bx = &g_boxes[(b * NPATCH + k) * 4];
                bx[0] = x1; bx[1] = y1; bx[2] = x2; bx[3] = y2;
                float* oc = out_coords + (b * NPATCH + k) * 4;
                oc[0] = (float)x1; oc[1] = (float)y1;
                oc[2] = (float)x2; oc[3] = (float)y2;
                scount = 0;
            }
            __syncthreads();
            if (k == NPATCH - 1) break;

            // classify tiles vs new expanded box
            {
                const int ex1 = sebox[k][0], ey1 = sebox[k][1];
                const int ex2 = sebox[k][2], ey2 = sebox[k][3];
                const int tx1 = (t & (TPD - 1)) * TILE, ty1 = (t >> 4) * TILE;
                const int tx2 = tx1 + TILE, ty2 = ty1 + TILE;
                if ((tx1 < ex2) && (tx2 > ex1) && (ty1 < ey2) && (ty2 > ey1)) {
                    if ((tx1 >= ex1) && (tx2 <= ex2) && (ty1 >= ey1) && (ty2 <= ey2))
                        stile[t] = 0ULL;
                    else
                        slist[atomicAdd(&scount, 1)] = t;
                }
            }
            __syncthreads();

            // warp-per-tile rescan of boundary tiles (8 warps)
            const int cnt = scount;
            for (int li = wid; li < cnt; li += 8) {
                const int tile = slist[li];
                const int tx1 = (tile & (TPD - 1)) * TILE;
                const int ty1 = (tile >> 4) * TILE;

                float4 f[8];
#pragma unroll
                for (int q = 0; q < 8; q++) {
                    const int f4 = q * 32 + lane;
                    const int y = ty1 + (f4 >> 3);
                    const int x = tx1 + ((f4 & 7) << 2);
                    f[q] = *(const float4*)(um + (y << 9) + x);
                }

                float m = -3.4e38f; int idx = 0;
#pragma unroll
                for (int q = 0; q < 8; q++) {
                    const int f4 = q * 32 + lane;
                    const int y = ty1 + (f4 >> 3);
                    const int x = tx1 + ((f4 & 7) << 2);
                    unsigned mask = 0;
                    for (int j = 0; j <= k; j++) {
                        if (y >= sebox[j][1] && y < sebox[j][3]) {
                            const int lo = max(sebox[j][0] - x, 0);
                            const int hi = min(sebox[j][2] - x, 4);
                            if (hi > lo) mask |= ((1u << (hi - lo)) - 1u) << lo;
                        }
                    }
                    const int gi = (y << 9) + x;
                    const float vals[4] = {f[q].x, f[q].y, f[q].z, f[q].w};
#pragma unroll
                    for (int e = 0; e < 4; e++)
                        if (!((mask >> e) & 1u) && vals[e] > m) { m = vals[e]; idx = gi + e; }
                }

                unsigned long long best =
                    ((unsigned long long)flipf(m) << 32) | (unsigned)~(unsigned)idx;
#pragma unroll
                for (int off = 16; off > 0; off >>= 1) {
                    unsigned long long o = __shfl_down_sync(0xFFFFFFFFu, best, off);
                    best = (o > best) ? o : best;
                }
                if (lane == 0) stile[tile] = best;
            }
        }
        __syncthreads();
        if (t == 0) { __threadfence(); atomicExch(&g_flag[b], 1); }
    }

    // ---------------- Phase 3: extract (all blocks, own batch) --------------
    if (t == 0) {
        while (atomicAdd(&g_flag[b], 0) == 0) __nanosleep(32);
    }
    __syncthreads();
    __threadfence();

#pragma unroll
    for (int r = 0; r < 3; r++) {
        const int q = i * 3 + r;                 // 0..47 within batch
        const int sub = q & 3;                   // quarter (32 rows)
        const int pc = q >> 2;                   // 0..11
        const int c = pc % C;
        const int n = pc / C;

        const int x1 = g_boxes[(b * NPATCH + n) * 4 + 0];
        const int y1 = g_boxes[(b * NPATCH + n) * 4 + 1];

        const float* __restrict__ src =
            images + (((size_t)(b * C + c) * HW) + y1 + sub * 32) * HW + x1;
        float4* __restrict__ dst =
            (float4*)(out + (size_t)((b * NPATCH + n) * C + c) * (P * P)) + sub * 1024;

        float4 rr[4];
#pragma unroll
        for (int it = 0; it < 4; it++) {
            const int v = it * 256 + t;          // 0..1023 f4 within quarter
            const int row = v >> 5;
            const int col = (v & 31) * 4;
            const float* s = src + (size_t)row * HW + col;
            rr[it] = make_float4(s[0], s[1], s[2], s[3]);
        }
#pragma unroll
        for (int it = 0; it < 4; it++)
            __stcs(&dst[it * 256 + t], rr[it]);
    }

    // ---------------- Epilogue: reset flags for next (graph) call -----------
    __syncthreads();
    if (t == 0) {
        if (i != 0) {
            atomicAdd(&g_done[b], 1);
        } else {
            while (atomicAdd(&g_done[b], 0) < BPB - 1) __nanosleep(32);
            g_done[b] = 0;
            atomicExch(&g_flag[b], 0);
        }
    }
}

// ---------------------------------------------------------------------------
extern "C" void kernel_launch(void* const* d_in, const int* in_sizes, int n_in,
                              void* d_out, int out_size) {
    const float* images = (const float*)d_in[0];   // [32,3,512,512]
    const float* umaps  = (const float*)d_in[1];   // [32,1,512,512]
    float* out = (float*)d_out;
    float* out_coords = out + PATCH_OUT_ELEMS;

    k_fused<<<GRID, 256>>>(images, umaps, out, out_coords);
}

// round 13
// speedup vs baseline: 1.2381x; 1.2381x over previous
#include <cuda_runtime.h>
#include <cstdint>

#define B 32
#define HW 512
#define NPIX (HW * HW)
#define NPATCH 4
#define C 3
#define P 128
#define HALF 64
#define MARGIN 32
#define TILE 32
#define TPD (HW / TILE)          // 16
#define NTILE (TPD * TPD)        // 256
#define NHALF (NTILE * 2)        // 512 half-tiles per map (16x32 px)
#define PATCH_OUT_ELEMS (B * NPATCH * C * P * P)

__device__ unsigned long long g_half[B * NHALF];
__device__ int g_boxes[B * NPATCH * 4];

__device__ __forceinline__ unsigned flipf(float v) {
    unsigned ub = __float_as_uint(v);
    return (ub & 0x80000000u) ? ~ub : (ub | 0x80000000u);
}

__device__ __forceinline__ unsigned smem_u32(const void* p) {
    return (unsigned)__cvta_generic_to_shared(p);
}

// ---------------------------------------------------------------------------
// Pass A: cp.async-staged scan. 1024 blocks; block = one 16-row strip (32KB)
// of one batch. LDGSTS fills smem (deep in-flight, no reg pressure); 8 warps
// then reduce 16 half-tiles (16x32 px) from smem with redux.sync.
// ---------------------------------------------------------------------------
__global__ __launch_bounds__(256)
void k_tilemax(const float* __restrict__ umap) {
    const int strip = blockIdx.x;            // 0..1023
    const int b = strip >> 5;                // batch
    const int s = strip & 31;                // strip within map (16 rows)
    const int t = threadIdx.x;
    const int lane = t & 31, wid = t >> 5;

    __shared__ float4 sm[2048];              // 32KB = 16 rows x 512 cols

    const float4* __restrict__ src =
        (const float4*)(umap + ((size_t)b << 18) + (s << 13));  // s*16*512

    // stage strip into smem via cp.async (8 x 16B per thread)
#pragma unroll
    for (int r = 0; r < 8; r++) {
        const unsigned dst = smem_u32(&sm[r * 256 + t]);
        asm volatile("cp.async.cg.shared.global [%0], [%1], 16;\n"
                     :: "r"(dst), "l"(src + r * 256 + t));
    }
    asm volatile("cp.async.commit_group;\n");
    asm volatile("cp.async.wait_group 0;\n");
    __syncthreads();

    // each warp reduces half-tiles tx = wid and wid+8
#pragma unroll
    for (int rep = 0; rep < 2; rep++) {
        const int tx = wid + rep * 8;        // 0..15

        float4 f[4];
        int yy[4], xx[4];
#pragma unroll
        for (int q = 0; q < 4; q++) {
            const int f4i = q * 32 + lane;   // 0..127
            const int y = f4i >> 3;          // 0..15 (strip-local row)
            const int xq = f4i & 7;          // f4 within 32-col half-tile
            yy[q] = y; xx[q] = xq;
            f[q] = sm[y * 128 + tx * 8 + xq];
        }

        float c4[4];
#pragma unroll
        for (int q = 0; q < 4; q++)
            c4[q] = fmaxf(fmaxf(f[q].x, f[q].y), fmaxf(f[q].z, f[q].w));
        const float m = fmaxf(fmaxf(c4[0], c4[1]), fmaxf(c4[2], c4[3]));

        const unsigned fm = flipf(m);
        const unsigned rmax = __reduce_max_sync(0xFFFFFFFFu, fm);

        int idx = 0x7FFFFFFF;
        if (fm == rmax) {
#pragma unroll
            for (int q = 0; q < 4; q++) {
                if (c4[q] == m) {
                    const int gi = ((s * 16 + yy[q]) << 9) + tx * 32 + xx[q] * 4;
                    if (f[q].x == m) idx = min(idx, gi);
                    if (f[q].y == m) idx = min(idx, gi + 1);
                    if (f[q].z == m) idx = min(idx, gi + 2);
                    if (f[q].w == m) idx = min(idx, gi + 3);
                }
            }
        }
        const unsigned rid = __reduce_min_sync(0xFFFFFFFFu, (unsigned)idx);

        if (lane == 0) {
            const int hid = 32 * (s >> 1) + 2 * tx + (s & 1);
            g_half[b * NHALF + hid] =
                ((unsigned long long)rmax << 32) | (unsigned)~rid;
        }
    }
}

// ---------------------------------------------------------------------------
// Pass B: fused 4-round greedy selection. One 1024-thr block per batch.
// ---------------------------------------------------------------------------
__global__ __launch_bounds__(1024)
void k_select(const float* __restrict__ umap, float* __restrict__ out_coords) {
    const int b = blockIdx.x;
    const int t = threadIdx.x;
    const int lane = t & 31, wid = t >> 5;
    const float* __restrict__ um = umap + ((size_t)b << 18);

    __shared__ unsigned long long stile[NTILE];
    __shared__ unsigned long long sred[32];
    __shared__ int sebox[NPATCH][4];
    __shared__ int slist[64];
    __shared__ int scount;

    if (t < NTILE) {
        const unsigned long long a = g_half[b * NHALF + 2 * t];
        const unsigned long long c = g_half[b * NHALF + 2 * t + 1];
        stile[t] = (a > c) ? a : c;     // packed order preserves first-occurrence
    }

    for (int k = 0; k < NPATCH; k++) {
        __syncthreads();
        unsigned long long v = (t < NTILE) ? stile[t] : 0ULL;
#pragma unroll
        for (int off = 16; off > 0; off >>= 1) {
            unsigned long long o = __shfl_down_sync(0xFFFFFFFFu, v, off);
            v = (o > v) ? o : v;
        }
        if (lane == 0) sred[wid] = v;
        __syncthreads();
        if (t == 0) {
            unsigned long long w = sred[0];
#pragma unroll
            for (int j = 1; j < 8; j++) w = (sred[j] > w) ? sred[j] : w;
            const int idx = (int)(~(unsigned)(w & 0xFFFFFFFFu));
            const int yc = idx >> 9, xc = idx & (HW - 1);

            int x1 = max(0, xc - HALF), x2 = min(HW, xc + HALF);
            if (x2 - x1 < P) { if (x1 == 0) x2 = P; else x1 = x2 - P; }
            int y1 = max(0, yc - HALF), y2 = min(HW, yc + HALF);
            if (y2 - y1 < P) { if (y1 == 0) y2 = P; else y1 = y2 - P; }

            sebox[k][0] = x1 - MARGIN; sebox[k][1] = y1 - MARGIN;
            sebox[k][2] = x2 + MARGIN; sebox[k][3] = y2 + MARGIN;

            int* bx = &g_boxes[(b * NPATCH + k) * 4];
            bx[0] = x1; bx[1] = y1; bx[2] = x2; bx[3] = y2;
            float* oc = out_coords + (b * NPATCH + k) * 4;
            oc[0] = (float)x1; oc[1] = (float)y1;
            oc[2] = (float)x2; oc[3] = (float)y2;
            scount = 0;
        }
        __syncthreads();
        if (k == NPATCH - 1) break;

        // classify tiles vs newly added expanded box
        if (t < NTILE) {
            const int ex1 = sebox[k][0], ey1 = sebox[k][1];
            const int ex2 = sebox[k][2], ey2 = sebox[k][3];
            const int tx1 = (t & (TPD - 1)) * TILE, ty1 = (t >> 4) * TILE;
            const int tx2 = tx1 + TILE, ty2 = ty1 + TILE;
            if ((tx1 < ex2) && (tx2 > ex1) && (ty1 < ey2) && (ty2 > ey1)) {
                if ((tx1 >= ex1) && (tx2 <= ex2) && (ty1 >= ey1) && (ty2 <= ey2))
                    stile[t] = 0ULL;
                else
                    slist[atomicAdd(&scount, 1)] = t;
            }
        }
        __syncthreads();

        // warp-per-tile rescan of boundary tiles against boxes 0..k
        const int cnt = scount;
        for (int li = wid; li < cnt; li += 32) {
            const int tile = slist[li];
            const int tx1 = (tile & (TPD - 1)) * TILE;
            const int ty1 = (tile >> 4) * TILE;

            float4 f[8];
#pragma unroll
            for (int q = 0; q < 8; q++) {
                const int f4 = q * 32 + lane;
                const int y = ty1 + (f4 >> 3);
                const int x = tx1 + ((f4 & 7) << 2);
                f[q] = *(const float4*)(um + (y << 9) + x);
            }

            float m = -3.4e38f; int idx = 0;
#pragma unroll
            for (int q = 0; q < 8; q++) {
                const int f4 = q * 32 + lane;
                const int y = ty1 + (f4 >> 3);
                const int x = tx1 + ((f4 & 7) << 2);
                unsigned mask = 0;
                for (int j = 0; j <= k; j++) {
                    if (y >= sebox[j][1] && y < sebox[j][3]) {
                        const int lo = max(sebox[j][0] - x, 0);
                        const int hi = min(sebox[j][2] - x, 4);
                        if (hi > lo) mask |= ((1u << (hi - lo)) - 1u) << lo;
                    }
                }
                const int gi = (y << 9) + x;
                const float vals[4] = {f[q].x, f[q].y, f[q].z, f[q].w};
#pragma unroll
                for (int e = 0; e < 4; e++)
                    if (!((mask >> e) & 1u) && vals[e] > m) { m = vals[e]; idx = gi + e; }
            }

            unsigned long long best =
                ((unsigned long long)flipf(m) << 32) | (unsigned)~(unsigned)idx;
#pragma unroll
            for (int off = 16; off > 0; off >>= 1) {
                unsigned long long o = __shfl_down_sync(0xFFFFFFFFu, best, off);
                best = (o > best) ? o : best;
            }
            if (lane == 0) stile[tile] = best;
        }
    }
}

// ---------------------------------------------------------------------------
// Pass C: extract. 768 half-patch blocks x 256 thr, 8 f4/thread (128B of
// reads in flight per thread). Streaming stores.
// ---------------------------------------------------------------------------
__global__ __launch_bounds__(256)
void k_extract(const float* __restrict__ images, float* __restrict__ out) {
    const int task = blockIdx.x;             // 0..767
    const int half = task & 1;               // 64-row half
    const int pc = task >> 1;
    const int c = pc % C;
    const int n = (pc / C) % NPATCH;
    const int b = pc / (C * NPATCH);

    const int x1 = g_boxes[(b * NPATCH + n) * 4 + 0];
    const int y1 = g_boxes[(b * NPATCH + n) * 4 + 1];

    const float* __restrict__ src =
        images + (((size_t)(b * C + c) * HW) + y1 + half * 64) * HW + x1;
    float4* __restrict__ dst =
        (float4*)(out + (size_t)((b * NPATCH + n) * C + c) * (P * P)) + half * 2048;

    float4 r[8];
#pragma unroll
    for (int it = 0; it < 8; it++) {
        const int v = it * 256 + threadIdx.x;    // 0..2047 f4 within half
        const int row = v >> 5;                   // 0..63
        const int col = (v & 31) * 4;
        const float* s = src + (size_t)row * HW + col;
        r[it] = make_float4(s[0], s[1], s[2], s[3]);
    }
#pragma unroll
    for (int it = 0; it < 8; it++)
        __stcs(&dst[it * 256 + threadIdx.x], r[it]);
}

// ---------------------------------------------------------------------------
extern "C" void kernel_launch(void* const* d_in, const int* in_sizes, int n_in,
                              void* d_out, int out_size) {
    const float* images = (const float*)d_in[0];   // [32,3,512,512]
    const float* umaps  = (const float*)d_in[1];   // [32,1,512,512]
    float* out = (float*)d_out;
    float* out_coords = out + PATCH_OUT_ELEMS;

    k_tilemax<<<B * 32, 256>>>(umaps);
    k_select<<<B, 1024>>>(umaps, out_coords);
    k_extract<<<B * NPATCH * C * 2, 256>>>(images, out);
}